// round 16
// baseline (speedup 1.0000x reference)
#include <cuda_runtime.h>
#include <cuda_fp16.h>

// ---------------------------------------------------------------------------
// CGCNN: B=16, N=1024, M=12, F=64, BF=128, N_CONV=3, VOCAB=100
// total@W = x@W1 + gather(x@W2) + bond@W3 ; proj fused into conv/prep.
// R16: proj rewritten as (row, col-quad) items: broadcast xs LDS + float4 W
// LDG; epilogue pb hoisted (nt-outer loops). GEMM: bond_h @ W_h fp16.
// ---------------------------------------------------------------------------

#define BN_ALPHA 0.99950037f   // 1/sqrt(1+1e-3)

__device__ float g_X0[16 * 1024 * 64];
__device__ float g_X1[16 * 1024 * 64];
__device__ float g_Y1[2][16 * 1024 * 64];
__device__ float g_Y2[2][16 * 1024 * 64];
__device__ float g_S1[2][16 * 1024];
__device__ float g_S2[2][16 * 1024];
__device__ float g_FL[3][16 * 1024 * 12];         // bond @ fw3 (fp32, exact)
__device__ __half g_WA[3][8192];                  // W frag-order fp16
__device__ __half g_BB[1024ull * 192 * 136];      // bond fp16 blobs, 52KB/tile

// ---- mbarrier / bulk helpers ----------------------------------------------
__device__ __forceinline__ void mbar_init(unsigned m, unsigned c) {
    asm volatile("mbarrier.init.shared.b64 [%0], %1;" ::"r"(m), "r"(c)
                 : "memory");
}
__device__ __forceinline__ void mbar_expect(unsigned m, unsigned b) {
    asm volatile("mbarrier.arrive.expect_tx.shared.b64 _, [%0], %1;" ::"r"(m),
                 "r"(b)
                 : "memory");
}
__device__ __forceinline__ void mbar_wait(unsigned m) {
    asm volatile(
        "{\n\t.reg .pred P;\n\tW%=:\n\t"
        "mbarrier.try_wait.parity.acquire.cta.shared::cta.b64 P, [%0], 0;\n\t"
        "@!P bra W%=;\n\t}" ::"r"(m)
        : "memory");
}
__device__ __forceinline__ void bulk_cp(unsigned d, const void* s, unsigned b,
                                        unsigned m) {
    asm volatile(
        "cp.async.bulk.shared::cta.global.mbarrier::complete_tx::bytes "
        "[%0], [%1], %2, [%3];" ::"r"(d),
        "l"(s), "r"(b), "r"(m)
        : "memory");
}

// ---- tensor-core helpers (sm_80+ PTX) -------------------------------------
__device__ __forceinline__ void mma16816(float* d, const unsigned* a,
                                         const unsigned* b) {
    asm volatile(
        "mma.sync.aligned.m16n8k16.row.col.f32.f16.f16.f32 "
        "{%0,%1,%2,%3}, {%4,%5,%6,%7}, {%8,%9}, {%0,%1,%2,%3};"
        : "+f"(d[0]), "+f"(d[1]), "+f"(d[2]), "+f"(d[3])
        : "r"(a[0]), "r"(a[1]), "r"(a[2]), "r"(a[3]), "r"(b[0]), "r"(b[1]));
}
__device__ __forceinline__ void ldmx4(unsigned* a, unsigned addr) {
    asm volatile(
        "ldmatrix.sync.aligned.m8n8.x4.shared.b16 {%0,%1,%2,%3}, [%4];"
        : "=r"(a[0]), "=r"(a[1]), "=r"(a[2]), "=r"(a[3])
        : "r"(addr));
}

// ---------------------------------------------------------------------------
// proj_quad: one row (smem xs, stride 68) x one col-quad -> Y1/Y2 buffer yb.
// q in [0,32): q<16 -> Y1 cols 4q.., q>=16 -> Y2 cols 4(q-16)..
// Warp-uniform row => xs LDS are broadcasts; W LDG coalesced float4.
// ---------------------------------------------------------------------------
__device__ __forceinline__ void proj_quad(const float* __restrict__ xs,
                                          int bn0, int row, int q, int yb,
                                          const float* __restrict__ cwn) {
    const float* wp = cwn + (q < 16 ? q * 4 : 4096 + (q - 16) * 4);
    float4 acc = make_float4(0.f, 0.f, 0.f, 0.f);
    const float* xr = xs + row * 68;
#pragma unroll 8
    for (int k = 0; k < 64; k++) {
        float xv = xr[k];
        float4 wv = __ldg((const float4*)(wp + k * 64));
        acc.x += xv * wv.x;
        acc.y += xv * wv.y;
        acc.z += xv * wv.z;
        acc.w += xv * wv.w;
    }
    float* dst = (q < 16 ? g_Y1[yb] : g_Y2[yb]) + (bn0 + row) * 64 +
                 (q & 15) * 4;
    *(float4*)dst = acc;
}

// S1/S2 scalar dot: one (atom, which) pair.
__device__ __forceinline__ void proj_s(const float* __restrict__ xs, int bn0,
                                       int a, int which, int yb,
                                       const float* __restrict__ fwn) {
    const float* wp = fwn + which * 64;
    const float* xr = xs + a * 68;
    float acc = 0.f;
#pragma unroll 8
    for (int k = 0; k < 64; k++) acc += xr[k] * __ldg(wp + k);
    if (which)
        g_S2[yb][bn0 + a] = acc;
    else
        g_S1[yb][bn0 + a] = acc;
}

// ---------------------------------------------------------------------------
// prep_k (merged): per 16-atom tile —
//  (a) bond fp16 image 192x136 + exact fp32 filter logits (3 layers),
//  (b) embedding gather + layer-0 projection (Y/S buffer 0),
//  (c) blocks 0-2: W fp16 fragment-order prep for layer blockIdx.x.
// grid 1024 x 256.
// ---------------------------------------------------------------------------
__global__ void __launch_bounds__(256) prep_k(
    const float* __restrict__ bond, const float* __restrict__ filt_w,
    const int* __restrict__ types, const float* __restrict__ emb,
    const float* __restrict__ core_w) {
    __shared__ float sfw[384];
    __shared__ float xs[16 * 68];
    int tid = threadIdx.x;
    size_t tile = blockIdx.x;
    int bn0 = blockIdx.x * 16;

    for (int t = tid; t < 384; t += 256) {
        int l = t >> 7, q = t & 127;
        sfw[t] = filt_w[l * 256 + 128 + q];
    }
    {   // embed: 16 atoms x 16 float4
        int r = tid >> 4, q = tid & 15;
        int ty = types[bn0 + r];
        float4 v = *(const float4*)(emb + ty * 64 + q * 4);
        *(float4*)(xs + r * 68 + q * 4) = v;
        *(float4*)(g_X0 + (bn0 + r) * 64 + q * 4) = v;
    }
    __syncthreads();

    // (a) bond conversion + logits
    const float* src = bond + tile * 192 * 128;
    __half* dh = g_BB + tile * 26112;
    for (int i = tid; i < 192 * 16; i += 256) {
        int row = i >> 4, q = i & 15;
        const float* s = src + row * 128 + q * 8;
        float4 v0 = *(const float4*)s;
        float4 v1 = *(const float4*)(s + 4);
        float v[8] = {v0.x, v0.y, v0.z, v0.w, v1.x, v1.y, v1.z, v1.w};
        unsigned hu[4];
#pragma unroll
        for (int p = 0; p < 4; p++) {
            __half2 hh;
            hh.x = __float2half(v[2 * p]);
            hh.y = __float2half(v[2 * p + 1]);
            hu[p] = reinterpret_cast<unsigned&>(hh);
        }
        *(uint4*)(dh + row * 136 + q * 8) =
            make_uint4(hu[0], hu[1], hu[2], hu[3]);
        float p0 = 0.f, p1 = 0.f, p2 = 0.f;
#pragma unroll
        for (int p = 0; p < 8; p++) {
            float vv = v[p];
            p0 += vv * sfw[q * 8 + p];
            p1 += vv * sfw[128 + q * 8 + p];
            p2 += vv * sfw[256 + q * 8 + p];
        }
#pragma unroll
        for (int off = 8; off; off >>= 1) {
            p0 += __shfl_xor_sync(0xFFFFFFFFu, p0, off);
            p1 += __shfl_xor_sync(0xFFFFFFFFu, p1, off);
            p2 += __shfl_xor_sync(0xFFFFFFFFu, p2, off);
        }
        if ((tid & 15) == 0) {
            size_t gr = tile * 192 + row;
            g_FL[0][gr] = p0;
            g_FL[1][gr] = p1;
            g_FL[2][gr] = p2;
        }
    }

    // (b) layer-0 projection: 512 quad items (16 rows x 32 quads) + 32 S
    for (int it = tid; it < 512; it += 256) {
        int row = it >> 5, q = it & 31;
        proj_quad(xs, bn0, row, q, 0, core_w);
    }
    if (tid < 32) proj_s(xs, bn0, tid >> 1, tid & 1, 0, filt_w);

    // (c) W prep for 3 layers
    if (blockIdx.x < 3) {
        int l = blockIdx.x;
        const float* W = core_w + l * 256 * 64 + 128 * 64;   // [k][n]
        __half2* outp = (__half2*)g_WA[l];
        for (int t = tid; t < 4096; t += 256) {
            int r = t & 1;
            int lane = (t >> 1) & 31;
            int nt = (t >> 6) & 1, wn = (t >> 7) & 3, ks = t >> 9;
            int n = wn * 16 + nt * 8 + (lane >> 2);
            int k = ks * 16 + (lane & 3) * 2 + r * 8;
            __half2 hh;
            hh.x = __float2half(W[k * 64 + n]);
            hh.y = __float2half(W[(k + 1) * 64 + n]);
            outp[t] = hh;
        }
    }
}

// ---------------------------------------------------------------------------
// conv_k: one block = 8 atoms (96 rows), 256 threads, 4 blocks/SM.
// 8 warps = 2 row-groups (48) x 4 col-groups (16); 48 mma/warp.
// smem (bytes): 16 mbar | 1024 sB(26112) | 27136 sW(16384) | 43520 ft(384) |
// 43904 nb(384) | 44288 xb(2176) | 46464 pb(1280) | 47744 y1s(2048) -> 49792
// reuse after GEMM: CsH(fp16 96x68) = sW region.
// ---------------------------------------------------------------------------
#define CONV_SMEM 49792

__global__ void __launch_bounds__(256, 4) conv_k(
    int l, int flip, int yrd, int ywr, const int* __restrict__ nbrl,
    const float* __restrict__ cb, const float* __restrict__ fb,
    const float* __restrict__ bag, const float* __restrict__ bab,
    const float* __restrict__ bbg, const float* __restrict__ bbb, int do_proj,
    const float* __restrict__ cwn, const float* __restrict__ fwn) {
    extern __shared__ char smem[];
    unsigned sbase = (unsigned)__cvta_generic_to_shared(smem);
    float* ft = (float*)(smem + 43520);
    int* nb = (int*)(smem + 43904);
    float* xb = (float*)(smem + 44288);
    float* pb = (float*)(smem + 46464);
    float* y1s = (float*)(smem + 47744);
    __half* CsH = (__half*)(smem + 27136);  // reuse sW after GEMM
    unsigned mb0 = sbase + 16;

    const float* Xc = flip ? g_X1 : g_X0;
    float* Xn = flip ? g_X0 : g_X1;
    const float* Y1r = g_Y1[yrd];
    const float* Y2r = g_Y2[yrd];
    const float* S1r = g_S1[yrd];
    const float* S2r = g_S2[yrd];

    int tid = threadIdx.x;
    int lane = tid & 31, w = tid >> 5;
    int bn0 = blockIdx.x * 8;          // 8 atoms per block
    int b = bn0 >> 10;

    if (tid == 0) {
        mbar_init(mb0, 1);
        mbar_expect(mb0, 26112 + 16384);
    }
    __syncthreads();

    size_t tile = blockIdx.x >> 1;
    unsigned half = blockIdx.x & 1;
    const char* bh = (const char*)(g_BB + tile * 26112) + half * 26112;

    if (tid == 0) {
        bulk_cp(sbase + 1024, bh, 26112, mb0);
    } else if (tid == 1) {
        bulk_cp(sbase + 27136, (const char*)&g_WA[l][0], 16384, mb0);
    } else if (tid >= 2 && tid < 98) {
        // pre-GEMM: nb + ft (precomputed fp32 logits) — overlaps TMA
        int row = tid - 2;
        int a_ = row / 12, m = row - a_ * 12;
        int nbr = nbrl[(bn0 + a_) * 12 + m];
        nb[row] = nbr;
        ft[row] = __ldg(&g_FL[l][(size_t)blockIdx.x * 96 + row]) +
                  S1r[bn0 + a_] + S2r[b * 1024 + nbr] + fb[0];
    }
    if (tid >= 128) {
        // y1 stage (8 atoms x 16 quads) — overlaps TMA
        int a = (tid - 128) >> 4, q = tid & 15;
        *(float4*)(y1s + a * 64 + q * 4) =
            *(const float4*)(Y1r + (bn0 + a) * 64 + q * 4);
    }
    if (tid >= 192) {
        int c = tid - 192;
        pb[c] = cb[c];
        pb[64 + c] = bag[c];
        pb[128 + c] = bab[c];
        pb[192 + c] = bbg[c];
        pb[256 + c] = bbb[c];
    }
    __syncthreads();
    if (tid < 8) {   // softmax over m (folds the 1/12 mean)
        int base = tid * 12;
        float mx = -1e30f;
#pragma unroll
        for (int m = 0; m < 12; m++) mx = fmaxf(mx, ft[base + m]);
        float s = 0.f;
#pragma unroll
        for (int m = 0; m < 12; m++) s += expf(ft[base + m] - mx);
        float inv = 1.f / (12.f * s);
#pragma unroll
        for (int m = 0; m < 12; m++)
            ft[base + m] = expf(ft[base + m] - mx) * inv;
    }

    // ---- GEMM: bond_h @ W_h (fp16, 48 mma/warp) ----
    int wm = w & 1, wn = w >> 1;
    unsigned laneoff = ((lane & 15) * 136 + (lane >> 4) * 8) * 2;
    const uint2* WH = (const uint2*)(smem + 27136);
    float d[3][2][4];
#pragma unroll
    for (int mt = 0; mt < 3; mt++)
#pragma unroll
        for (int nt = 0; nt < 2; nt++)
#pragma unroll
            for (int fr = 0; fr < 4; fr++) d[mt][nt][fr] = 0.f;

    mbar_wait(mb0);
    {
        unsigned abase = sbase + 1024 + laneoff + (unsigned)(wm * 48 * 272);
#pragma unroll
        for (int ks = 0; ks < 8; ks++) {
            unsigned bfr[2][2];
#pragma unroll
            for (int nt = 0; nt < 2; nt++) {
                uint2 vH = WH[(ks * 8 + wn * 2 + nt) * 32 + lane];
                bfr[nt][0] = vH.x;
                bfr[nt][1] = vH.y;
            }
#pragma unroll
            for (int mt = 0; mt < 3; mt++) {
                unsigned afr[4];
                ldmx4(afr, abase + mt * (16 * 272) + ks * 32);
                mma16816(d[mt][0], afr, bfr[0]);
                mma16816(d[mt][1], afr, bfr[1]);
            }
        }
    }
    __syncthreads();   // all warps done reading sW -> CsH may overwrite

    // ---- epilogue (nt outer, pb hoisted): frag + y1s + y2(LDG) + cb ->
    //      BN -> relu -> CsH (fp16)
#pragma unroll
    for (int nt = 0; nt < 2; nt++) {
        int c0 = wn * 16 + nt * 8 + (lane & 3) * 2;
        float ga = pb[64 + c0], gb_ = pb[64 + c0 + 1];
        float ba = pb[128 + c0], bb_ = pb[128 + c0 + 1];
        float cba = pb[c0], cbb = pb[c0 + 1];
#pragma unroll
        for (int mt = 0; mt < 3; mt++) {
            int rbase = wm * 48 + mt * 16 + (lane >> 2);
#pragma unroll
            for (int h = 0; h < 2; h++) {
                int row = rbase + h * 8;
                int a_ = row / 12;
                int nbr = nb[row];
                float2 y2v =
                    *(const float2*)(Y2r + (b * 1024 + nbr) * 64 + c0);
                float2 y1v = *(const float2*)(y1s + a_ * 64 + c0);
                float v0 = d[mt][nt][2 * h] + y1v.x + y2v.x + cba;
                float v1 = d[mt][nt][2 * h + 1] + y1v.y + y2v.y + cbb;
                v0 = fmaxf(ga * (v0 * BN_ALPHA) + ba, 0.f);
                v1 = fmaxf(gb_ * (v1 * BN_ALPHA) + bb_, 0.f);
                __half2 hv;
                hv.x = __float2half(v0);
                hv.y = __float2half(v1);
                *(__half2*)(CsH + row * 68 + c0) = hv;
            }
        }
    }
    __syncthreads();

    // ---- weighted mean (half2 single pass), BN, residual relu; stash xn ----
    {
        int a_ = tid >> 5;         // 8 atoms
        int c = (tid & 31) * 2;    // col pair
        float s0 = 0.f, s1 = 0.f;
#pragma unroll
        for (int m = 0; m < 12; m++) {
            float wgt = ft[a_ * 12 + m];
            __half2 hv = *(const __half2*)(CsH + (a_ * 12 + m) * 68 + c);
            float2 fv = __half22float2(hv);
            s0 += wgt * fv.x;
            s1 += wgt * fv.y;
        }
        s0 = pb[192 + c] * (s0 * BN_ALPHA) + pb[256 + c];
        s1 = pb[192 + c + 1] * (s1 * BN_ALPHA) + pb[256 + c + 1];
        int gi = (bn0 + a_) * 64 + c;
        float2 xc = *(const float2*)(Xc + gi);
        float xv0 = fmaxf(xc.x + s0, 0.f);
        float xv1 = fmaxf(xc.y + s1, 0.f);
        *(float2*)(Xn + gi) = make_float2(xv0, xv1);
        xb[a_ * 68 + c] = xv0;
        xb[a_ * 68 + c + 1] = xv1;
    }
    __syncthreads();

    // ---- fused next-layer projection: 256 quad items + 16 S dots ----
    if (do_proj) {
        int row = tid >> 5, q = tid & 31;
        proj_quad(xb, bn0, row, q, ywr, cwn);
        if (tid < 16) proj_s(xb, bn0, tid >> 1, tid & 1, ywr, fwn);
    }
}

// ---------------------------------------------------------------------------
__global__ void __launch_bounds__(256) final_k(const int* __restrict__ tix,
                                               const float* __restrict__ dw,
                                               const float* __restrict__ db,
                                               float* __restrict__ out) {
    __shared__ float cs[64 * 68];
    __shared__ float wd[64 * 65];
    int b = blockIdx.x, tid = threadIdx.x;
    for (int t = tid; t < 4096; t += 256) {
        int k = t >> 6, f = t & 63;
        wd[k * 65 + f] = dw[t];
    }
    for (int t = tid; t < 1024; t += 256) {
        int j = t >> 4, q = t & 15;
        int ti = tix[b * 64 + j];
        float4 v = *(const float4*)(g_X1 + (b * 1024 + ti) * 64 + q * 4);
        v.x = fmaxf(v.x, 0.f);
        v.y = fmaxf(v.y, 0.f);
        v.z = fmaxf(v.z, 0.f);
        v.w = fmaxf(v.w, 0.f);
        *(float4*)(cs + j * 68 + q * 4) = v;
    }
    __syncthreads();
    for (int t = tid; t < 4096; t += 256) {
        int j = t >> 6, f = t & 63;
        float acc = db[f];
#pragma unroll 8
        for (int k = 0; k < 64; k++) acc += cs[j * 68 + k] * wd[k * 65 + f];
        out[b * 4096 + t] = fmaxf(acc, 0.f);
    }
}

// ---------------------------------------------------------------------------
extern "C" void kernel_launch(void* const* d_in, const int* in_sizes, int n_in,
                              void* d_out, int out_size) {
    const int* atom_types = (const int*)d_in[0];
    const float* bond = (const float*)d_in[1];
    const int* nbrl = (const int*)d_in[2];
    const int* tix = (const int*)d_in[3];
    const float* emb = (const float*)d_in[4];
    const float* core_w = (const float*)d_in[5];
    const float* core_b = (const float*)d_in[6];
    const float* filt_w = (const float*)d_in[7];
    const float* filt_b = (const float*)d_in[8];
    const float* bna_g = (const float*)d_in[9];
    const float* bna_b = (const float*)d_in[10];
    const float* bnb_g = (const float*)d_in[11];
    const float* bnb_b = (const float*)d_in[12];
    const float* dw = (const float*)d_in[13];
    const float* db = (const float*)d_in[14];
    float* out = (float*)d_out;

    cudaFuncSetAttribute(conv_k, cudaFuncAttributeMaxDynamicSharedMemorySize,
                         CONV_SMEM);

    prep_k<<<1024, 256>>>(bond, filt_w, atom_types, emb, core_w);
    for (int l = 0; l < 3; l++) {
        int flip = l & 1;
        int yrd = l & 1;
        int ywr = (l + 1) & 1;
        int do_proj = (l < 2) ? 1 : 0;
        const float* cwn = core_w + (l + 1 < 3 ? (l + 1) : l) * 256 * 64;
        const float* fwn = filt_w + (l + 1 < 3 ? (l + 1) : l) * 256;
        conv_k<<<2048, 256, CONV_SMEM>>>(
            l, flip, yrd, ywr, nbrl, core_b + l * 64, filt_b + l,
            bna_g + l * 64, bna_b + l * 64, bnb_g + l * 64, bnb_b + l * 64,
            do_proj, cwn, fwn);
    }
    final_k<<<16, 256>>>(tix, dw, db, out);
}

// round 17
// speedup vs baseline: 1.0545x; 1.0545x over previous
#include <cuda_runtime.h>
#include <cuda_fp16.h>

// ---------------------------------------------------------------------------
// CGCNN: B=16, N=1024, M=12, F=64, BF=128, N_CONV=3, VOCAB=100
// total@W = x@W1 + gather(x@W2) + bond@W3 ; proj fused into conv/prep.
// R17: proj4 restored (coalesced W reads); logits moved into conv (fp16 tile,
// warps 0-2 pre-GEMM) -> g_FL + prep shfl storm removed.
// GEMM: bond_h @ W_h fp16.
// ---------------------------------------------------------------------------

#define BN_ALPHA 0.99950037f   // 1/sqrt(1+1e-3)

__device__ float g_X0[16 * 1024 * 64];
__device__ float g_X1[16 * 1024 * 64];
__device__ float g_Y1[2][16 * 1024 * 64];
__device__ float g_Y2[2][16 * 1024 * 64];
__device__ float g_S1[2][16 * 1024];
__device__ float g_S2[2][16 * 1024];
__device__ __half g_WA[3][8192];                  // W frag-order fp16
__device__ __half g_BB[1024ull * 192 * 136];      // bond fp16 blobs, 52KB/tile

// ---- mbarrier / bulk helpers ----------------------------------------------
__device__ __forceinline__ void mbar_init(unsigned m, unsigned c) {
    asm volatile("mbarrier.init.shared.b64 [%0], %1;" ::"r"(m), "r"(c)
                 : "memory");
}
__device__ __forceinline__ void mbar_expect(unsigned m, unsigned b) {
    asm volatile("mbarrier.arrive.expect_tx.shared.b64 _, [%0], %1;" ::"r"(m),
                 "r"(b)
                 : "memory");
}
__device__ __forceinline__ void mbar_wait(unsigned m) {
    asm volatile(
        "{\n\t.reg .pred P;\n\tW%=:\n\t"
        "mbarrier.try_wait.parity.acquire.cta.shared::cta.b64 P, [%0], 0;\n\t"
        "@!P bra W%=;\n\t}" ::"r"(m)
        : "memory");
}
__device__ __forceinline__ void bulk_cp(unsigned d, const void* s, unsigned b,
                                        unsigned m) {
    asm volatile(
        "cp.async.bulk.shared::cta.global.mbarrier::complete_tx::bytes "
        "[%0], [%1], %2, [%3];" ::"r"(d),
        "l"(s), "r"(b), "r"(m)
        : "memory");
}

// ---- tensor-core helpers (sm_80+ PTX) -------------------------------------
__device__ __forceinline__ void mma16816(float* d, const unsigned* a,
                                         const unsigned* b) {
    asm volatile(
        "mma.sync.aligned.m16n8k16.row.col.f32.f16.f16.f32 "
        "{%0,%1,%2,%3}, {%4,%5,%6,%7}, {%8,%9}, {%0,%1,%2,%3};"
        : "+f"(d[0]), "+f"(d[1]), "+f"(d[2]), "+f"(d[3])
        : "r"(a[0]), "r"(a[1]), "r"(a[2]), "r"(a[3]), "r"(b[0]), "r"(b[1]));
}
__device__ __forceinline__ void ldmx4(unsigned* a, unsigned addr) {
    asm volatile(
        "ldmatrix.sync.aligned.m8n8.x4.shared.b16 {%0,%1,%2,%3}, [%4];"
        : "=r"(a[0]), "=r"(a[1]), "=r"(a[2]), "=r"(a[3])
        : "r"(addr));
}

// ---------------------------------------------------------------------------
// proj4: 4 rows of x (smem, stride 68) -> Y1/Y2/S1/S2 buffer yb.
// Thread = c2 (consecutive c2 lanes -> coalesced W LDG; xs LDS broadcast).
// ---------------------------------------------------------------------------
__device__ __forceinline__ void proj4(const float* __restrict__ xs, int bn0,
                                      int r0, int c2, int yb,
                                      const float* __restrict__ cwn,
                                      const float* __restrict__ fwn) {
    const float* wp;
    int st;
    if (c2 < 64) {
        wp = cwn + c2;
        st = 64;
    } else if (c2 < 128) {
        wp = cwn + 64 * 64 + (c2 - 64);
        st = 64;
    } else {
        wp = fwn + (c2 - 128) * 64;
        st = 1;
    }
    float acc[4] = {0.f, 0.f, 0.f, 0.f};
#pragma unroll 2
    for (int k = 0; k < 64; k += 4) {
        float4 xv[4];
#pragma unroll
        for (int rr = 0; rr < 4; rr++)
            xv[rr] = *(const float4*)(xs + (r0 + rr) * 68 + k);
#pragma unroll
        for (int j = 0; j < 4; j++) {
            float wv = __ldg(wp + (k + j) * st);
#pragma unroll
            for (int rr = 0; rr < 4; rr++)
                acc[rr] += ((const float*)&xv[rr])[j] * wv;
        }
    }
    if (c2 < 64) {
#pragma unroll
        for (int rr = 0; rr < 4; rr++)
            g_Y1[yb][(bn0 + r0 + rr) * 64 + c2] = acc[rr];
    } else if (c2 < 128) {
#pragma unroll
        for (int rr = 0; rr < 4; rr++)
            g_Y2[yb][(bn0 + r0 + rr) * 64 + (c2 - 64)] = acc[rr];
    } else if (c2 == 128) {
#pragma unroll
        for (int rr = 0; rr < 4; rr++) g_S1[yb][bn0 + r0 + rr] = acc[rr];
    } else {
#pragma unroll
        for (int rr = 0; rr < 4; rr++) g_S2[yb][bn0 + r0 + rr] = acc[rr];
    }
}

// ---------------------------------------------------------------------------
// prep_k (merged): per 16-atom tile —
//  (a) bond fp16 image 192x136 (no logits — done in conv now),
//  (b) embedding gather + layer-0 projection (Y/S buffer 0),
//  (c) blocks 0-2: W fp16 fragment-order prep for layer blockIdx.x.
// grid 1024 x 256.
// ---------------------------------------------------------------------------
__global__ void __launch_bounds__(256) prep_k(
    const float* __restrict__ bond, const float* __restrict__ filt_w,
    const int* __restrict__ types, const float* __restrict__ emb,
    const float* __restrict__ core_w) {
    __shared__ float xs[16 * 68];
    int tid = threadIdx.x;
    size_t tile = blockIdx.x;
    int bn0 = blockIdx.x * 16;

    {   // embed: 16 atoms x 16 float4
        int r = tid >> 4, q = tid & 15;
        int ty = types[bn0 + r];
        float4 v = *(const float4*)(emb + ty * 64 + q * 4);
        *(float4*)(xs + r * 68 + q * 4) = v;
        *(float4*)(g_X0 + (bn0 + r) * 64 + q * 4) = v;
    }
    __syncthreads();

    // (a) bond conversion (coalesced 16B-chunk mapping)
    const float* src = bond + tile * 192 * 128;
    __half* dh = g_BB + tile * 26112;
    for (int i = tid; i < 192 * 16; i += 256) {
        int row = i >> 4, q = i & 15;
        const float* s = src + row * 128 + q * 8;
        float4 v0 = *(const float4*)s;
        float4 v1 = *(const float4*)(s + 4);
        unsigned hu[4];
        __half2 h0, h1, h2, h3;
        h0.x = __float2half(v0.x);
        h0.y = __float2half(v0.y);
        h1.x = __float2half(v0.z);
        h1.y = __float2half(v0.w);
        h2.x = __float2half(v1.x);
        h2.y = __float2half(v1.y);
        h3.x = __float2half(v1.z);
        h3.y = __float2half(v1.w);
        hu[0] = reinterpret_cast<unsigned&>(h0);
        hu[1] = reinterpret_cast<unsigned&>(h1);
        hu[2] = reinterpret_cast<unsigned&>(h2);
        hu[3] = reinterpret_cast<unsigned&>(h3);
        *(uint4*)(dh + row * 136 + q * 8) =
            make_uint4(hu[0], hu[1], hu[2], hu[3]);
    }

    // (b) layer-0 projection: 520 items = 130 c2 x 4 row-quads
    for (int it = tid; it < 520; it += 256) {
        int c2 = it % 130, rh = it / 130;
        proj4(xs, bn0, rh * 4, c2, 0, core_w, filt_w);
    }

    // (c) W prep for 3 layers
    if (blockIdx.x < 3) {
        int l = blockIdx.x;
        const float* W = core_w + l * 256 * 64 + 128 * 64;   // [k][n]
        __half2* outp = (__half2*)g_WA[l];
        for (int t = tid; t < 4096; t += 256) {
            int r = t & 1;
            int lane = (t >> 1) & 31;
            int nt = (t >> 6) & 1, wn = (t >> 7) & 3, ks = t >> 9;
            int n = wn * 16 + nt * 8 + (lane >> 2);
            int k = ks * 16 + (lane & 3) * 2 + r * 8;
            __half2 hh;
            hh.x = __float2half(W[k * 64 + n]);
            hh.y = __float2half(W[(k + 1) * 64 + n]);
            outp[t] = hh;
        }
    }
}

// ---------------------------------------------------------------------------
// conv_k: one block = 8 atoms (96 rows), 256 threads, 4 blocks/SM.
// 8 warps = 2 row-groups (48) x 4 col-groups (16); 48 mma/warp.
// Logits computed from fp16 smem tile by warps 0-2 (pre-GEMM, warp slack).
// smem (bytes): 16 mbar | 1024 sB(26112) | 27136 sW(16384) | 43520 ft(384) |
// 43904 nb(384) | 44288 xb(2176) | 46464 pb(1280) | 47744 y1s(2048) |
// 49792 fs(512) -> 50304.  CsH(fp16 96x68) reuses sW after GEMM.
// ---------------------------------------------------------------------------
#define CONV_SMEM 50304

__global__ void __launch_bounds__(256, 4) conv_k(
    int l, int flip, int yrd, int ywr, const int* __restrict__ nbrl,
    const float* __restrict__ fw3, const float* __restrict__ cb,
    const float* __restrict__ fb, const float* __restrict__ bag,
    const float* __restrict__ bab, const float* __restrict__ bbg,
    const float* __restrict__ bbb, int do_proj,
    const float* __restrict__ cwn, const float* __restrict__ fwn) {
    extern __shared__ char smem[];
    unsigned sbase = (unsigned)__cvta_generic_to_shared(smem);
    __half* sB = (__half*)(smem + 1024);
    float* ft = (float*)(smem + 43520);
    int* nb = (int*)(smem + 43904);
    float* xb = (float*)(smem + 44288);
    float* pb = (float*)(smem + 46464);
    float* y1s = (float*)(smem + 47744);
    float* fs = (float*)(smem + 49792);
    __half* CsH = (__half*)(smem + 27136);  // reuse sW after GEMM
    unsigned mb0 = sbase + 16;

    const float* Xc = flip ? g_X1 : g_X0;
    float* Xn = flip ? g_X0 : g_X1;
    const float* Y1r = g_Y1[yrd];
    const float* Y2r = g_Y2[yrd];
    const float* S1r = g_S1[yrd];
    const float* S2r = g_S2[yrd];

    int tid = threadIdx.x;
    int lane = tid & 31, w = tid >> 5;
    int bn0 = blockIdx.x * 8;          // 8 atoms per block
    int b = bn0 >> 10;

    if (tid == 0) {
        mbar_init(mb0, 1);
        mbar_expect(mb0, 26112 + 16384);
    }
    __syncthreads();

    size_t tile = blockIdx.x >> 1;
    unsigned half = blockIdx.x & 1;
    const char* bh = (const char*)(g_BB + tile * 26112) + half * 26112;

    if (tid == 0) {
        bulk_cp(sbase + 1024, bh, 26112, mb0);
    } else if (tid == 1) {
        bulk_cp(sbase + 27136, (const char*)&g_WA[l][0], 16384, mb0);
    } else if (tid >= 2 && tid < 98) {
        // ft base = S1 + S2[nbr] + fb  (logit dot added post-TMA)
        int row = tid - 2;
        int a_ = row / 12, m = row - a_ * 12;
        int nbr = nbrl[(bn0 + a_) * 12 + m];
        nb[row] = nbr;
        ft[row] = S1r[bn0 + a_] + S2r[b * 1024 + nbr] + fb[0];
    }
    if (tid < 128) fs[tid] = __ldg(fw3 + tid);
    if (tid >= 128) {
        int a = (tid - 128) >> 4, q = tid & 15;
        *(float4*)(y1s + a * 64 + q * 4) =
            *(const float4*)(Y1r + (bn0 + a) * 64 + q * 4);
    }
    if (tid >= 192) {
        int c = tid - 192;
        pb[c] = cb[c];
        pb[64 + c] = bag[c];
        pb[128 + c] = bab[c];
        pb[192 + c] = bbg[c];
        pb[256 + c] = bbb[c];
    }
    __syncthreads();

    mbar_wait(mb0);

    // ---- logits: warps 0-2 (one row each) from fp16 tile; hides in warp
    //      slack vs warps 3-7 that go straight to mma ----
    if (tid < 96) {
        const __half* pr = sB + tid * 136;
        float acc = 0.f;
#pragma unroll
        for (int k = 0; k < 128; k += 8) {
            uint4 u = *(const uint4*)(pr + k);
            float2 f0 = __half22float2(reinterpret_cast<__half2&>(u.x));
            float2 f1 = __half22float2(reinterpret_cast<__half2&>(u.y));
            float2 f2 = __half22float2(reinterpret_cast<__half2&>(u.z));
            float2 f3 = __half22float2(reinterpret_cast<__half2&>(u.w));
            acc += f0.x * fs[k] + f0.y * fs[k + 1] + f1.x * fs[k + 2] +
                   f1.y * fs[k + 3] + f2.x * fs[k + 4] + f2.y * fs[k + 5] +
                   f3.x * fs[k + 6] + f3.y * fs[k + 7];
        }
        ft[tid] += acc;
    }

    // ---- GEMM: bond_h @ W_h (fp16, 48 mma/warp) ----
    int wm = w & 1, wn = w >> 1;
    unsigned laneoff = ((lane & 15) * 136 + (lane >> 4) * 8) * 2;
    const uint2* WH = (const uint2*)(smem + 27136);
    float d[3][2][4];
#pragma unroll
    for (int mt = 0; mt < 3; mt++)
#pragma unroll
        for (int nt = 0; nt < 2; nt++)
#pragma unroll
            for (int fr = 0; fr < 4; fr++) d[mt][nt][fr] = 0.f;

    {
        unsigned abase = sbase + 1024 + laneoff + (unsigned)(wm * 48 * 272);
#pragma unroll
        for (int ks = 0; ks < 8; ks++) {
            unsigned bfr[2][2];
#pragma unroll
            for (int nt = 0; nt < 2; nt++) {
                uint2 vH = WH[(ks * 8 + wn * 2 + nt) * 32 + lane];
                bfr[nt][0] = vH.x;
                bfr[nt][1] = vH.y;
            }
#pragma unroll
            for (int mt = 0; mt < 3; mt++) {
                unsigned afr[4];
                ldmx4(afr, abase + mt * (16 * 272) + ks * 32);
                mma16816(d[mt][0], afr, bfr[0]);
                mma16816(d[mt][1], afr, bfr[1]);
            }
        }
    }
    __syncthreads();   // sW reads done (CsH may overwrite); ft complete

    // ---- softmax (tid<8, folds 1/12 mean) then epilogue (all threads) ----
    if (tid < 8) {
        int base = tid * 12;
        float mx = -1e30f;
#pragma unroll
        for (int m = 0; m < 12; m++) mx = fmaxf(mx, ft[base + m]);
        float s = 0.f;
#pragma unroll
        for (int m = 0; m < 12; m++) s += expf(ft[base + m] - mx);
        float inv = 1.f / (12.f * s);
#pragma unroll
        for (int m = 0; m < 12; m++)
            ft[base + m] = expf(ft[base + m] - mx) * inv;
    }

    // epilogue (nt outer, pb hoisted): frag + y1s + y2(LDG) + cb -> BN ->
    // relu -> CsH (fp16)
#pragma unroll
    for (int nt = 0; nt < 2; nt++) {
        int c0 = wn * 16 + nt * 8 + (lane & 3) * 2;
        float ga = pb[64 + c0], gb_ = pb[64 + c0 + 1];
        float ba = pb[128 + c0], bb_ = pb[128 + c0 + 1];
        float cba = pb[c0], cbb = pb[c0 + 1];
#pragma unroll
        for (int mt = 0; mt < 3; mt++) {
            int rbase = wm * 48 + mt * 16 + (lane >> 2);
#pragma unroll
            for (int h = 0; h < 2; h++) {
                int row = rbase + h * 8;
                int a_ = row / 12;
                int nbr = nb[row];
                float2 y2v =
                    *(const float2*)(Y2r + (b * 1024 + nbr) * 64 + c0);
                float2 y1v = *(const float2*)(y1s + a_ * 64 + c0);
                float v0 = d[mt][nt][2 * h] + y1v.x + y2v.x + cba;
                float v1 = d[mt][nt][2 * h + 1] + y1v.y + y2v.y + cbb;
                v0 = fmaxf(ga * (v0 * BN_ALPHA) + ba, 0.f);
                v1 = fmaxf(gb_ * (v1 * BN_ALPHA) + bb_, 0.f);
                __half2 hv;
                hv.x = __float2half(v0);
                hv.y = __float2half(v1);
                *(__half2*)(CsH + row * 68 + c0) = hv;
            }
        }
    }
    __syncthreads();

    // ---- weighted mean (half2 single pass), BN, residual relu; stash xn ----
    {
        int a_ = tid >> 5;         // 8 atoms
        int c = (tid & 31) * 2;    // col pair
        float s0 = 0.f, s1 = 0.f;
#pragma unroll
        for (int m = 0; m < 12; m++) {
            float wgt = ft[a_ * 12 + m];
            __half2 hv = *(const __half2*)(CsH + (a_ * 12 + m) * 68 + c);
            float2 fv = __half22float2(hv);
            s0 += wgt * fv.x;
            s1 += wgt * fv.y;
        }
        s0 = pb[192 + c] * (s0 * BN_ALPHA) + pb[256 + c];
        s1 = pb[192 + c + 1] * (s1 * BN_ALPHA) + pb[256 + c + 1];
        int gi = (bn0 + a_) * 64 + c;
        float2 xc = *(const float2*)(Xc + gi);
        float xv0 = fmaxf(xc.x + s0, 0.f);
        float xv1 = fmaxf(xc.y + s1, 0.f);
        *(float2*)(Xn + gi) = make_float2(xv0, xv1);
        xb[a_ * 68 + c] = xv0;
        xb[a_ * 68 + c + 1] = xv1;
    }
    __syncthreads();

    // ---- fused next-layer projection: 260 items (130 c2 x 2 row-quads) ----
    if (do_proj) {
        for (int it = tid; it < 260; it += 256) {
            int c2 = it % 130, rh = it / 130;
            proj4(xb, bn0, rh * 4, c2, ywr, cwn, fwn);
        }
    }
}

// ---------------------------------------------------------------------------
__global__ void __launch_bounds__(256) final_k(const int* __restrict__ tix,
                                               const float* __restrict__ dw,
                                               const float* __restrict__ db,
                                               float* __restrict__ out) {
    __shared__ float cs[64 * 68];
    __shared__ float wd[64 * 65];
    int b = blockIdx.x, tid = threadIdx.x;
    for (int t = tid; t < 4096; t += 256) {
        int k = t >> 6, f = t & 63;
        wd[k * 65 + f] = dw[t];
    }
    for (int t = tid; t < 1024; t += 256) {
        int j = t >> 4, q = t & 15;
        int ti = tix[b * 64 + j];
        float4 v = *(const float4*)(g_X1 + (b * 1024 + ti) * 64 + q * 4);
        v.x = fmaxf(v.x, 0.f);
        v.y = fmaxf(v.y, 0.f);
        v.z = fmaxf(v.z, 0.f);
        v.w = fmaxf(v.w, 0.f);
        *(float4*)(cs + j * 68 + q * 4) = v;
    }
    __syncthreads();
    for (int t = tid; t < 4096; t += 256) {
        int j = t >> 6, f = t & 63;
        float acc = db[f];
#pragma unroll 8
        for (int k = 0; k < 64; k++) acc += cs[j * 68 + k] * wd[k * 65 + f];
        out[b * 4096 + t] = fmaxf(acc, 0.f);
    }
}

// ---------------------------------------------------------------------------
extern "C" void kernel_launch(void* const* d_in, const int* in_sizes, int n_in,
                              void* d_out, int out_size) {
    const int* atom_types = (const int*)d_in[0];
    const float* bond = (const float*)d_in[1];
    const int* nbrl = (const int*)d_in[2];
    const int* tix = (const int*)d_in[3];
    const float* emb = (const float*)d_in[4];
    const float* core_w = (const float*)d_in[5];
    const float* core_b = (const float*)d_in[6];
    const float* filt_w = (const float*)d_in[7];
    const float* filt_b = (const float*)d_in[8];
    const float* bna_g = (const float*)d_in[9];
    const float* bna_b = (const float*)d_in[10];
    const float* bnb_g = (const float*)d_in[11];
    const float* bnb_b = (const float*)d_in[12];
    const float* dw = (const float*)d_in[13];
    const float* db = (const float*)d_in[14];
    float* out = (float*)d_out;

    cudaFuncSetAttribute(conv_k, cudaFuncAttributeMaxDynamicSharedMemorySize,
                         CONV_SMEM);

    prep_k<<<1024, 256>>>(bond, filt_w, atom_types, emb, core_w);
    for (int l = 0; l < 3; l++) {
        int flip = l & 1;
        int yrd = l & 1;
        int ywr = (l + 1) & 1;
        int do_proj = (l < 2) ? 1 : 0;
        const float* cwn = core_w + (l + 1 < 3 ? (l + 1) : l) * 256 * 64;
        const float* fwn = filt_w + (l + 1 < 3 ? (l + 1) : l) * 256;
        conv_k<<<2048, 256, CONV_SMEM>>>(
            l, flip, yrd, ywr, nbrl, filt_w + l * 256 + 128, core_b + l * 64,
            filt_b + l, bna_g + l * 64, bna_b + l * 64, bnb_g + l * 64,
            bnb_b + l * 64, do_proj, cwn, fwn);
    }
    final_k<<<16, 256>>>(tix, dw, db, out);
}